// round 5
// baseline (speedup 1.0000x reference)
#include <cuda_runtime.h>
#include <cuda_fp16.h>
#include <math.h>
#include <stdint.h>

// ===========================================================================
// Scratch (device globals; no allocation allowed)
// B=4, S=4096, D=512 -> M = 16384
// ===========================================================================
#define MAXELEM (16384 * 512)
#define MAXPH   (4096 * 512)
#define WELEM   (512 * 512)

__device__ __align__(256) __half g_h[7][MAXELEM];    // xh,Kh,Qh,NBh,KMh,QMh,Vh
__device__ __align__(256) __half g_wh[6][WELEM];     // 6 fp16 weights
__device__ float g_cb[MAXPH];
__device__ float g_sb[MAXPH];

// ===========================================================================
// helpers
// ===========================================================================
__device__ __forceinline__ uint32_t smem_to_u32(const void* smem_ptr) {
    uint32_t addr;
    asm("{ .reg .u64 tmp; cvta.to.shared.u64 tmp, %1; cvt.u32.u64 %0, tmp; }"
        : "=r"(addr) : "l"(smem_ptr));
    return addr;
}

__device__ __forceinline__ void ldsm_x4(uint32_t& r0, uint32_t& r1,
                                        uint32_t& r2, uint32_t& r3, uint32_t a) {
    asm volatile("ldmatrix.sync.aligned.m8n8.x4.shared.b16 {%0,%1,%2,%3}, [%4];\n"
                 : "=r"(r0), "=r"(r1), "=r"(r2), "=r"(r3) : "r"(a));
}

__device__ __forceinline__ void mma16816(float* c, const uint32_t* a,
                                         const uint32_t* b) {
    asm volatile(
        "mma.sync.aligned.m16n8k16.row.col.f32.f16.f16.f32 "
        "{%0,%1,%2,%3},{%4,%5,%6,%7},{%8,%9},{%0,%1,%2,%3};\n"
        : "+f"(c[0]), "+f"(c[1]), "+f"(c[2]), "+f"(c[3])
        : "r"(a[0]), "r"(a[1]), "r"(a[2]), "r"(a[3]), "r"(b[0]), "r"(b[1]));
}

// ===========================================================================
// base-phase cos/sin table
// ===========================================================================
__global__ void phase_table_kernel(const float* __restrict__ bp,
                                   float* __restrict__ cb,
                                   float* __restrict__ sb, int n) {
    int i = blockIdx.x * blockDim.x + threadIdx.x;
    if (i < n) {
        float s, c;
        sincosf(bp[i], &s, &c);
        cb[i] = c;
        sb[i] = s;
    }
}

// ===========================================================================
// fp32 -> fp16 converters
// ===========================================================================
__global__ void tohalf_kernel(const float4* __restrict__ src,
                              __half2* __restrict__ dst, int n4) {
    int i = blockIdx.x * blockDim.x + threadIdx.x;
    if (i < n4) {
        float4 v = src[i];
        dst[2 * i + 0] = __floats2half2_rn(v.x, v.y);
        dst[2 * i + 1] = __floats2half2_rn(v.z, v.w);
    }
}

__global__ void tohalf3_kernel(const float4* s0, const float4* s1,
                               const float4* s2, __half2* d0, __half2* d1,
                               __half2* d2, int n4) {
    int i = blockIdx.x * blockDim.x + threadIdx.x;
    if (i >= 3 * n4) return;
    int t = i / n4, j = i - t * n4;
    const float4* s = (t == 0) ? s0 : (t == 1) ? s1 : s2;
    __half2* d = (t == 0) ? d0 : (t == 1) ? d1 : d2;
    float4 v = s[j];
    d[2 * j + 0] = __floats2half2_rn(v.x, v.y);
    d[2 * j + 1] = __floats2half2_rn(v.z, v.w);
}

// ===========================================================================
// fp16 HMMA GEMM (NT), batched via blockIdx.z job select.
// Tile 128x128, KC=64, 256 threads (8 warps 2x4, each 64x32).
// 3-stage cp.async ring, ONE __syncthreads per chunk, prefetch distance 2.
// mode 1: outH = fp16(acc + bias)
// mode 2: outF = acc + bias + resid
// ===========================================================================
#define KC 64
#define ROWB 144
#define TILE_B (128 * ROWB)
#define STAGE_B (2 * TILE_B)          // 36864
#define NSTAGE 3
#define GEMM_SMEM (NSTAGE * STAGE_B)  // 110592

struct Job {
    const __half* A;
    const __half* W;
    const float*  bias;
    const float*  resid;
    float*        outF;
    __half*       outH;
    int           mode;
};

__global__ __launch_bounds__(256, 2) void gemm_h(
    Job j0, Job j1, Job j2, int M, int N, int K)
{
    extern __shared__ char smem[];
    const Job jb = (blockIdx.z == 0) ? j0 : (blockIdx.z == 1) ? j1 : j2;

    const uint32_t sbase = smem_to_u32(smem);
    const int tid = threadIdx.x;
    const int wid = tid >> 5, lane = tid & 31;
    const int bm = blockIdx.y * 128;
    const int bn = blockIdx.x * 128;
    const int wm = wid >> 2, wn = wid & 3;
    const int NCH = K / KC;

    const __half* Ab = jb.A + (size_t)bm * K;
    const __half* Wb = jb.W + (size_t)bn * K;

    auto load_chunk = [&](int kc, int s) {
        uint32_t st = sbase + s * STAGE_B;
        int koff = kc * KC;
        #pragma unroll
        for (int j = 0; j < 8; j++) {
            int q = tid + j * 256;
            int t = q >> 10;
            int r = (q >> 3) & 127;
            int seg = q & 7;
            const __half* src = (t ? Wb : Ab) + (size_t)r * K + koff + seg * 8;
            uint32_t dst = st + t * TILE_B + r * ROWB + seg * 16;
            asm volatile("cp.async.cg.shared.global [%0], [%1], 16;\n"
                         :: "r"(dst), "l"(src));
        }
        asm volatile("cp.async.commit_group;\n");
    };

    float acc[4][4][4];
    #pragma unroll
    for (int i = 0; i < 4; i++)
        #pragma unroll
        for (int j = 0; j < 4; j++)
            #pragma unroll
            for (int e = 0; e < 4; e++) acc[i][j][e] = 0.f;

    load_chunk(0, 0);
    load_chunk(1, 1);

    const uint32_t a_r = (lane & 15);
    const uint32_t a_k = (lane >> 4) * 16;
    const uint32_t b_r = (lane & 7) + ((lane >> 4) << 3);
    const uint32_t b_k = ((lane >> 3) & 1) * 16;

    for (int i = 0; i < NCH; i++) {
        int s = i % NSTAGE;
        // ensure chunk i's group completed (groups retire in order)
        if (i == NCH - 1)
            asm volatile("cp.async.wait_group 0;\n" ::: "memory");
        else
            asm volatile("cp.async.wait_group 1;\n" ::: "memory");
        __syncthreads();
        // stage (i+2)%NSTAGE == (i-1)%NSTAGE was last read at iter i-1,
        // which every warp finished before this barrier -> safe to refill.
        if (i + 2 < NCH) load_chunk(i + 2, (i + 2) % NSTAGE);

        uint32_t At = sbase + s * STAGE_B;
        uint32_t Wt = At + TILE_B;

        #pragma unroll
        for (int k16 = 0; k16 < 4; k16++) {
            uint32_t a[4][4];
            #pragma unroll
            for (int mi = 0; mi < 4; mi++) {
                uint32_t addr = At + (wm * 64 + mi * 16 + a_r) * ROWB
                              + k16 * 32 + a_k;
                ldsm_x4(a[mi][0], a[mi][1], a[mi][2], a[mi][3], addr);
            }
            uint32_t b[4][2];
            #pragma unroll
            for (int bp = 0; bp < 2; bp++) {
                uint32_t r0, r1, r2, r3;
                uint32_t addr = Wt + (wn * 32 + bp * 16 + b_r) * ROWB
                              + k16 * 32 + b_k;
                ldsm_x4(r0, r1, r2, r3, addr);
                b[2 * bp + 0][0] = r0; b[2 * bp + 0][1] = r1;
                b[2 * bp + 1][0] = r2; b[2 * bp + 1][1] = r3;
            }
            #pragma unroll
            for (int mi = 0; mi < 4; mi++)
                #pragma unroll
                for (int ni = 0; ni < 4; ni++)
                    mma16816(acc[mi][ni], a[mi], b[ni]);
        }
    }

    // epilogue
    const int r0 = bm + wm * 64 + (lane >> 2);
    const int c0 = bn + wn * 32 + (lane & 3) * 2;
    const int mode = jb.mode;
    #pragma unroll
    for (int mi = 0; mi < 4; mi++) {
        #pragma unroll
        for (int h = 0; h < 2; h++) {
            int row = r0 + mi * 16 + h * 8;
            #pragma unroll
            for (int ni = 0; ni < 4; ni++) {
                int col = c0 + ni * 8;
                size_t idx = (size_t)row * N + col;
                float2 bv = *(const float2*)(jb.bias + col);
                float v0 = acc[mi][ni][2 * h + 0] + bv.x;
                float v1 = acc[mi][ni][2 * h + 1] + bv.y;
                if (mode == 2) {
                    float2 rv = *(const float2*)(jb.resid + idx);
                    v0 += rv.x; v1 += rv.y;
                    float2 o; o.x = v0; o.y = v1;
                    *(float2*)(jb.outF + idx) = o;
                } else {
                    *(__half2*)(jb.outH + idx) = __floats2half2_rn(v0, v1);
                }
            }
        }
    }
}

// ===========================================================================
// Taylor sincos for tiny delta
// ===========================================================================
__device__ __forceinline__ void sincos_small(float x, float& s, float& c) {
    float x2 = x * x;
    s = x * fmaf(x2, fmaf(x2, fmaf(x2, -1.f / 5040.f, 1.f / 120.f), -1.f / 6.f), 1.f);
    c = fmaf(x2, fmaf(x2, fmaf(x2, -1.f / 720.f, 1.f / 24.f), -0.5f), 1.f);
}

// ===========================================================================
// Fused phasor bind + chunked cumsum + retrieval + LayerNorm -> fp16.
// Block = one (batch, chunk), 512 threads = one per feature d. Two barriers.
// ===========================================================================
#define CHK 64
#define NW  16

__global__ __launch_bounds__(512) void phasor_ln_kernel(
    const __half* __restrict__ V, const __half* __restrict__ KM,
    const __half* __restrict__ QM,
    const float* __restrict__ cb, const float* __restrict__ sbt,
    const float* __restrict__ msp,
    const float* __restrict__ lng, const float* __restrict__ lnb,
    __half* __restrict__ Oh, int S, int D)
{
    const int d = threadIdx.x;
    const int nC = S / CHK;
    const int b = blockIdx.x / nC;
    const int c = blockIdx.x % nC;

    const float ms  = msp[0];
    const float g   = lng[d];
    const float be  = lnb[d];
    const float inv = rsqrtf((float)D);

    const int lane = d & 31;
    const int w    = d >> 5;

    __shared__ float sm1[CHK * 17];
    __shared__ float sm2[CHK * 17];
    __shared__ float smu[CHK];
    __shared__ float srs[CHK];

    float r[CHK];
    float mr = 0.f, mi = 0.f;
    size_t base  = ((size_t)b * S + (size_t)c * CHK) * D + d;
    size_t pbase = ((size_t)c * CHK) * D + d;

    #pragma unroll
    for (int s = 0; s < CHK; s++) {
        size_t idx  = base + (size_t)s * D;
        size_t pidx = pbase + (size_t)s * D;

        float cbp = cb[pidx];
        float sbp = sbt[pidx];
        float dk = __half2float(KM[idx]) * ms;
        float dq = __half2float(QM[idx]) * ms;
        float sk, ck, sq, cq;
        sincos_small(dk, sk, ck);
        sincos_small(dq, sq, cq);

        float ckp = cbp * ck - sbp * sk;
        float skp = sbp * ck + cbp * sk;
        float cqp = cbp * cq - sbp * sq;
        float sqp = sbp * cq + cbp * sq;

        float v = __half2float(V[idx]);
        mr = fmaf(v, ckp, mr);
        mi = fmaf(v, skp, mi);

        float rv = (mr * cqp + mi * sqp) * inv;
        r[s] = rv;

        float s1 = rv, s2 = rv * rv;
        #pragma unroll
        for (int o = 16; o > 0; o >>= 1) {
            s1 += __shfl_xor_sync(0xffffffffu, s1, o);
            s2 += __shfl_xor_sync(0xffffffffu, s2, o);
        }
        if (lane == 0) { sm1[s * 17 + w] = s1; sm2[s * 17 + w] = s2; }
    }
    __syncthreads();

    if (d < CHK) {
        float a1 = 0.f, a2 = 0.f;
        #pragma unroll
        for (int j = 0; j < NW; j++) {
            a1 += sm1[d * 17 + j];
            a2 += sm2[d * 17 + j];
        }
        float mu = a1 / (float)D;
        smu[d] = mu;
        srs[d] = rsqrtf(a2 / (float)D - mu * mu + 1e-5f);
    }
    __syncthreads();

    #pragma unroll
    for (int s = 0; s < CHK; s++) {
        float normed = (r[s] - smu[s]) * srs[s] * g + be;
        Oh[base + (size_t)s * D] = __float2half(normed);
    }
}

// ===========================================================================
// Launch
// ===========================================================================
extern "C" void kernel_launch(void* const* d_in, const int* in_sizes, int n_in,
                              void* d_out, int out_size)
{
    const float* x    = (const float*)d_in[0];
    const float* bp   = (const float*)d_in[1];
    const float* Wk   = (const float*)d_in[2];
    const float* bk   = (const float*)d_in[3];
    const float* Wv   = (const float*)d_in[4];
    const float* bv   = (const float*)d_in[5];
    const float* Wq   = (const float*)d_in[6];
    const float* bq   = (const float*)d_in[7];
    const float* Wkm  = (const float*)d_in[8];
    const float* bkm  = (const float*)d_in[9];
    const float* Wqm  = (const float*)d_in[10];
    const float* bqm  = (const float*)d_in[11];
    const float* ms   = (const float*)d_in[12];
    const float* lng  = (const float*)d_in[13];
    const float* lnb  = (const float*)d_in[14];
    const float* Wo   = (const float*)d_in[15];
    const float* bo   = (const float*)d_in[16];
    float* out = (float*)d_out;

    const int D  = in_sizes[3];         // 512
    const int SD = in_sizes[1];         // S*D
    const int S  = SD / D;              // 4096
    const int M  = in_sizes[0] / D;     // 16384

    __half* hp = nullptr;   cudaGetSymbolAddress((void**)&hp, g_h);
    __half* whp = nullptr;  cudaGetSymbolAddress((void**)&whp, g_wh);
    float* cbuf = nullptr;  cudaGetSymbolAddress((void**)&cbuf, g_cb);
    float* sbuf = nullptr;  cudaGetSymbolAddress((void**)&sbuf, g_sb);

    __half* xh  = hp + 0L * MAXELEM;
    __half* Kh  = hp + 1L * MAXELEM;
    __half* Qh  = hp + 2L * MAXELEM;
    __half* NBh = hp + 3L * MAXELEM;
    __half* KMh = hp + 4L * MAXELEM;
    __half* QMh = hp + 5L * MAXELEM;
    __half* Vh  = hp + 6L * MAXELEM;

    __half* Wh[6];
    for (int j = 0; j < 6; j++) Wh[j] = whp + (size_t)j * WELEM;

    cudaFuncSetAttribute(gemm_h, cudaFuncAttributeMaxDynamicSharedMemorySize,
                         GEMM_SMEM);

    const int W4 = WELEM / 4;

    // 0: x -> fp16
    tohalf_kernel<<<(M * D / 4 + 255) / 256, 256>>>(
        (const float4*)x, (__half2*)xh, M * D / 4);
    // 1: Wk, Wv, Wq -> fp16
    tohalf3_kernel<<<(3 * W4 + 255) / 256, 256>>>(
        (const float4*)Wk, (const float4*)Wv, (const float4*)Wq,
        (__half2*)Wh[0], (__half2*)Wh[1], (__half2*)Wh[2], W4);
    // 2: Wkm, Wqm, Wo -> fp16
    tohalf3_kernel<<<(3 * W4 + 255) / 256, 256>>>(
        (const float4*)Wkm, (const float4*)Wqm, (const float4*)Wo,
        (__half2*)Wh[3], (__half2*)Wh[4], (__half2*)Wh[5], W4);

    dim3 g3(D / 128, M / 128, 3);
    dim3 g2(D / 128, M / 128, 2);
    dim3 g1(D / 128, M / 128, 1);

    Job jK  = { xh,  Wh[0], bk,  nullptr, nullptr, Kh,  1 };
    Job jV  = { xh,  Wh[1], bv,  nullptr, nullptr, Vh,  1 };
    Job jQ  = { xh,  Wh[2], bq,  nullptr, nullptr, Qh,  1 };
    Job jKM = { Kh,  Wh[3], bkm, nullptr, nullptr, KMh, 1 };
    Job jQM = { Qh,  Wh[4], bqm, nullptr, nullptr, QMh, 1 };
    Job jO  = { NBh, Wh[5], bo,  x,       out,     nullptr, 2 };

    // 3: K, V, Q  (target for ncu sample)
    gemm_h<<<g3, 256, GEMM_SMEM>>>(jK, jV, jQ, M, D, D);
    // 4: phase table (independent; overlaps GEMM tail in-order queue anyway)
    phase_table_kernel<<<(SD + 255) / 256, 256>>>(bp, cbuf, sbuf, SD);
    // 5: KM, QM
    gemm_h<<<g2, 256, GEMM_SMEM>>>(jKM, jQM, jQM, M, D, D);
    // 6: phasor + cumsum + retrieval + LayerNorm
    phasor_ln_kernel<<<(M / CHK), D>>>(Vh, KMh, QMh, cbuf, sbuf, ms, lng, lnb,
                                       NBh, S, D);
    // 7: out = x + normed@Wo^T + bo
    gemm_h<<<g1, 256, GEMM_SMEM>>>(jO, jO, jO, M, D, D);
}